// round 6
// baseline (speedup 1.0000x reference)
#include <cuda_runtime.h>

// Two-phase exact LIF via renewal speculation.
//
// Recurrence on pre-reset S:  S_t = (S_{t-1} > th) ? x_t : S_{t-1}+x_t,
// implemented as f = set.le(S,th); S = fma(S,f,x)  (bit-exact, proven R4).
//
// Phase 1: 32 time-chunks of 1024 steps per chain, all parallel. Chunks c>0
// start from S_entry = th+1 (>th, finite, positive) so the first exact step
// yields S0 = x0 — i.e. "assume a spike just before the chunk". Chunk 0 uses
// the true acc0 entry (exact). Writes full outs+spikes; stores chunk-exit
// states to __device__ scratch. Renewal property: the speculative trajectory
// becomes exact at the first step where the true trajectory also spikes.
//
// Phase 2: one thread per chain (1024) walks chunks in order, replaying the
// exact recurrence from the true entry and overwriting out/spike until the
// replay spikes at a step where the spec run spiked too (bitwise merge);
// then the rest of the chunk is already exact and the stored spec exit
// becomes the next chunk's true entry.

#define NB 16
#define NS 256
#define NH 128
#define NN 64
#define NPB 32
#define HT 128
#define CHUNK_S 8                    // s-rows per chunk
#define LCH (CHUNK_S * NH)           // 1024 steps per chunk
#define NC (NS / CHUNK_S)            // 32 chunks
#define RS 132
#define TT (NS * NH)
#define TOTE ((long long)NB * NS * NN * NH)

__device__ float g_exit[NB * 2 * NPB * NC];   // [chain][c]

#define STEPX(S, XV, TH) do {                                               \
    float f_;                                                               \
    asm("set.le.f32.f32 %0, %1, %2;" : "=f"(f_) : "f"(S), "f"(TH));         \
    asm("fma.rn.f32 %0, %1, %2, %3;" : "=f"(S) : "f"(S), "f"(f_), "f"(XV)); \
} while (0)

// ---------------- phase 1 ----------------

__device__ __forceinline__ void drain_tile(
    int b, int g, int s, const float* __restrict__ src,
    const float* __restrict__ thr_s, float* __restrict__ outbuf, int wl)
{
    float* ob = outbuf + (((long long)b * NS + s) * NN + g * NPB) * NH;
    float* sb = ob + TOTE;
    #pragma unroll
    for (int it = 0; it < 16; ++it) {
        int idx = wl + it * 64;
        int n = idx >> 5, q = idx & 31;
        float4 v = *(const float4*)(src + n * RS + q * 4);
        float th = thr_s[n];
        bool p0 = v.x > th, p1 = v.y > th, p2 = v.z > th, p3 = v.w > th;
        float4 o, sp;
        o.x = p0 ? v.x : 0.0f;  sp.x = p0 ? 1.0f : 0.0f;
        o.y = p1 ? v.y : 0.0f;  sp.y = p1 ? 1.0f : 0.0f;
        o.z = p2 ? v.z : 0.0f;  sp.z = p2 ? 1.0f : 0.0f;
        o.w = p3 ? v.w : 0.0f;  sp.w = p3 ? 1.0f : 0.0f;
        *(float4*)(ob + n * NH + q * 4) = o;
        *(float4*)(sb + n * NH + q * 4) = sp;
    }
}

__global__ __launch_bounds__(96, 1)
void lif_spec_kernel(const float* __restrict__ inputs,
                     const float* __restrict__ threshes,
                     const float* __restrict__ acc0,
                     float* __restrict__ outbuf)
{
    __shared__ float buf[2][NPB * RS];
    __shared__ float xs[2][HT];
    __shared__ float thr_s[NPB];

    const int idx  = blockIdx.x;            // 16 b x 2 grp x 32 chunks
    const int c    = idx & (NC - 1);
    const int g    = (idx >> 5) & 1;
    const int b    = idx >> 6;
    const int tid  = threadIdx.x;
    const int wid  = tid >> 5;
    const int lane = tid & 31;
    const int s0   = c * CHUNK_S;
    const float* xb = inputs + (long long)b * TT + (long long)c * LCH;

    if (tid < NPB) thr_s[tid] = threshes[g * NPB + tid];
    if (wid == 1)
        *(float4*)(&xs[0][lane * 4]) = *(const float4*)(xb + lane * 4);
    __syncthreads();

    if (wid == 0) {
        const float th = thr_s[lane];
        // c==0: true entry acc0 (chunk exact). c>0: th+1 > th, finite,
        // positive -> first exact step gives S0 = x0 (assumed spike).
        float S = (c == 0) ? acc0[b * NN + g * NPB + lane] : (th + 1.0f);
        for (int tt = 0; tt < CHUNK_S; ++tt) {
            const float* __restrict__ xr  = xs[tt & 1];
            float* __restrict__       row = &buf[tt & 1][lane * RS];
            #pragma unroll
            for (int j = 0; j < HT; j += 8) {
                float4 xa = *(const float4*)(xr + j);
                float4 xc = *(const float4*)(xr + j + 4);
                float4 a, e;
                STEPX(S, xa.x, th); a.x = S;
                STEPX(S, xa.y, th); a.y = S;
                STEPX(S, xa.z, th); a.z = S;
                STEPX(S, xa.w, th); a.w = S;
                STEPX(S, xc.x, th); e.x = S;
                STEPX(S, xc.y, th); e.y = S;
                STEPX(S, xc.z, th); e.z = S;
                STEPX(S, xc.w, th); e.w = S;
                *(float4*)(row + j)     = a;
                *(float4*)(row + j + 4) = e;
            }
            __syncthreads();
        }
        g_exit[((b * 2 + g) * NPB + lane) * NC + c] = S;   // chunk exit
    } else {
        const int wl = tid - 32;
        for (int tt = 0; tt < CHUNK_S; ++tt) {
            if (tt + 1 < CHUNK_S && wl < 32)
                *(float4*)(&xs[(tt + 1) & 1][wl * 4]) =
                    *(const float4*)(xb + (tt + 1) * HT + wl * 4);
            if (tt > 0)
                drain_tile(b, g, s0 + tt - 1, buf[(tt - 1) & 1], thr_s, outbuf, wl);
            __syncthreads();
        }
        drain_tile(b, g, s0 + CHUNK_S - 1, buf[(CHUNK_S - 1) & 1], thr_s, outbuf, wl);
    }
}

// ---------------- phase 2: sequential fix-up ----------------

__global__ __launch_bounds__(128, 1)
void lif_fix_kernel(const float* __restrict__ inputs,
                    const float* __restrict__ threshes,
                    float* __restrict__ outbuf)
{
    const int w    = blockIdx.x * 4 + (threadIdx.x >> 5);   // 0..31
    const int lane = threadIdx.x & 31;
    const int b    = w >> 1;
    const int g    = w & 1;
    const int n    = g * NPB + lane;
    const float th = threshes[n];
    const float* xb = inputs + (long long)b * TT;
    float* outp = outbuf;
    float* spkp = outbuf + TOTE;
    const int chain = (b * 2 + g) * NPB + lane;

    float S = g_exit[chain * NC + 0];        // chunk 0 is exact
    for (int c = 1; c < NC; ++c) {
        const int t0 = c * LCH;
        const int s0 = c * CHUNK_S;
        const long long rowoff = (((long long)b * NS + s0) * NN + n) * NH;
        const float* sp_row = spkp + rowoff;
        float*       ob_row = outp + rowoff;

        float ks[16], xv[16];
        *(float4*)&ks[0]  = *(const float4*)(sp_row + 0);
        *(float4*)&ks[4]  = *(const float4*)(sp_row + 4);
        *(float4*)&ks[8]  = *(const float4*)(sp_row + 8);
        *(float4*)&ks[12] = *(const float4*)(sp_row + 12);
        *(float4*)&xv[0]  = *(const float4*)(xb + t0 + 0);
        *(float4*)&xv[4]  = *(const float4*)(xb + t0 + 4);
        *(float4*)&xv[8]  = *(const float4*)(xb + t0 + 8);
        *(float4*)&xv[12] = *(const float4*)(xb + t0 + 12);

        bool merged = false;
        #pragma unroll
        for (int i = 0; i < 16; ++i) {
            if (!merged) {
                STEPX(S, xv[i], th);
                bool sp = S > th;
                if (sp && ks[i] != 0.0f) {       // joint spike -> merged
                    ob_row[i] = S;               // spec spike already 1
                    merged = true;
                } else {
                    ob_row[i] = sp ? S : 0.0f;
                    spkp[rowoff + i] = sp ? 1.0f : 0.0f;
                }
            }
        }
        // rare slow path: not merged within 16 steps
        for (int i = 16; i < LCH && !merged; ++i) {
            const int t = t0 + i;
            float x = xb[t];
            STEPX(S, x, th);
            bool sp = S > th;
            long long a = (((long long)b * NS + (t >> 7)) * NN + n) * NH + (t & 127);
            float spec = spkp[a];
            if (sp && spec != 0.0f) { outp[a] = S; merged = true; }
            else { outp[a] = sp ? S : 0.0f; spkp[a] = sp ? 1.0f : 0.0f; }
        }
        S = merged ? g_exit[chain * NC + c] : S;
    }
}

extern "C" void kernel_launch(void* const* d_in, const int* in_sizes, int n_in,
                              void* d_out, int out_size)
{
    const float* inputs   = (const float*)d_in[0];  // [B,S,H]
    const float* threshes = (const float*)d_in[1];  // [N]
    const float* acc0     = (const float*)d_in[2];  // [B,N]
    float* out = (float*)d_out;                     // outs then spikes (f32)

    lif_spec_kernel<<<NB * 2 * NC, 96>>>(inputs, threshes, acc0, out);
    lif_fix_kernel<<<8, 128>>>(inputs, threshes, out);
}

// round 7
// speedup vs baseline: 1.5674x; 1.5674x over previous
#include <cuda_runtime.h>

// LIF, single-kernel intra-block renewal speculation.
//
// Exact step on pre-reset S:  f = set.le(S,th); S = fma(S,f,x)   (proven R4/R6).
// Renewal: after any spike the state is x_{t+1} regardless of history, so a
// speculative trajectory started from "assumed spike" (entry S=th+1 => S0=x0)
// merges bitwise with the true one at the first JOINT spike.
//
// 32 blocks = 16 batches x 2 neuron-halves (32 neurons). 256 threads:
//   warps 0..3 : chain warp for time-quarter w (8192 steps), exact recurrence,
//                S tiles -> smem. Quarter 0 entry = acc0 (exact), else th+1.
//   warps 4..7 : drain warp paired with chain w: stages x tiles, drains S
//                tiles to global (coalesced STG.128). Pair syncs via named
//                barrier (w+1, 64) once per 32-step tile.
//   after __syncthreads: warp 0 replays each quarter boundary from the true
//   entry, patching out/spike until joint-spike merge, then adopts the
//   speculative quarter exit.

#define NB 16
#define NS 256
#define NH 128
#define NN 64
#define NPB 32
#define NQ 4
#define QLEN 8192                   // steps per quarter
#define HT2 32                      // steps per tile
#define NT2 (QLEN / HT2)            // 256 tiles per quarter
#define RS2 36                      // buf row stride (chunk 9n+q -> conflict-free STS)
#define TT (NS * NH)
#define TOTE ((long long)NB * NS * NN * NH)

#define STEPX(S, XV, TH) do {                                               \
    float f_;                                                               \
    asm("set.le.f32.f32 %0, %1, %2;" : "=f"(f_) : "f"(S), "f"(TH));         \
    asm("fma.rn.f32 %0, %1, %2, %3;" : "=f"(S) : "f"(S), "f"(f_), "f"(XV)); \
} while (0)

#define PAIR_BAR(W) asm volatile("bar.sync %0, %1;" :: "r"((W) + 1), "r"(64) : "memory")

__global__ __launch_bounds__(256, 1)
void lif_kernel(const float* __restrict__ inputs,
                const float* __restrict__ threshes,
                const float* __restrict__ acc0,
                float* __restrict__ outbuf)
{
    __shared__ float buf[NQ][2][NPB * RS2];   // 36.9 KB
    __shared__ float xs[NQ][2][HT2];          // 1 KB
    __shared__ float thr_s[NPB];
    __shared__ float qexit[NQ][NPB];

    const int b    = blockIdx.x >> 1;
    const int g    = blockIdx.x & 1;
    const int tid  = threadIdx.x;
    const int wid  = tid >> 5;
    const int lane = tid & 31;
    const float* xb = inputs + (long long)b * TT;
    float* outp = outbuf;
    float* spkp = outbuf + TOTE;

    // ---- prologue ----
    if (wid == 0) thr_s[lane] = threshes[g * NPB + lane];
    if (wid >= NQ) {                 // drain warp w stages x tile 0 of quarter w
        const int w = wid - NQ;
        if (lane < 8)
            *(float4*)&xs[w][0][lane * 4] =
                *(const float4*)(xb + w * QLEN + lane * 4);
    }
    __syncthreads();

    if (wid < NQ) {
        // ================= chain warp: quarter wid =================
        const int   w  = wid;
        const float th = thr_s[lane];
        float S = (w == 0) ? acc0[b * NN + g * NPB + lane] : (th + 1.0f);
        for (int tt = 0; tt < NT2; ++tt) {
            const float* __restrict__ xr  = xs[w][tt & 1];
            float* __restrict__       row = &buf[w][tt & 1][lane * RS2];
            #pragma unroll
            for (int j = 0; j < HT2; j += 8) {
                float4 xa = *(const float4*)(xr + j);       // broadcast LDS
                float4 xc = *(const float4*)(xr + j + 4);
                float4 a, e;
                STEPX(S, xa.x, th); a.x = S;
                STEPX(S, xa.y, th); a.y = S;
                STEPX(S, xa.z, th); a.z = S;
                STEPX(S, xa.w, th); a.w = S;
                STEPX(S, xc.x, th); e.x = S;
                STEPX(S, xc.y, th); e.y = S;
                STEPX(S, xc.z, th); e.z = S;
                STEPX(S, xc.w, th); e.w = S;
                *(float4*)(row + j)     = a;                // STS.128, 9n+q banks
                *(float4*)(row + j + 4) = e;
            }
            PAIR_BAR(w);
        }
        qexit[w][lane] = S;
    } else {
        // ================= drain warp: pair w =================
        const int w = wid - NQ;
        for (int tt = 0; tt < NT2; ++tt) {
            if (tt + 1 < NT2 && lane < 8)                    // stage next x tile
                *(float4*)&xs[w][(tt + 1) & 1][lane * 4] =
                    *(const float4*)(xb + w * QLEN + (tt + 1) * HT2 + lane * 4);
            if (tt > 0) {
                const int dt = tt - 1;
                const int s  = w * (QLEN / NH) + (dt >> 2);
                const int h0 = (dt & 3) * HT2;
                const float* src = buf[w][dt & 1];
                float* ob = outp + (((long long)b * NS + s) * NN + g * NPB) * NH + h0;
                float* sb = ob + TOTE;
                #pragma unroll
                for (int it = 0; it < 8; ++it) {
                    int idx = lane + it * 32;
                    int n = idx >> 3, q = idx & 7;
                    float4 v = *(const float4*)(src + n * RS2 + q * 4);
                    float th = thr_s[n];
                    bool p0 = v.x > th, p1 = v.y > th, p2 = v.z > th, p3 = v.w > th;
                    float4 o, sp;
                    o.x = p0 ? v.x : 0.0f;  sp.x = p0 ? 1.0f : 0.0f;
                    o.y = p1 ? v.y : 0.0f;  sp.y = p1 ? 1.0f : 0.0f;
                    o.z = p2 ? v.z : 0.0f;  sp.z = p2 ? 1.0f : 0.0f;
                    o.w = p3 ? v.w : 0.0f;  sp.w = p3 ? 1.0f : 0.0f;
                    *(float4*)(ob + n * NH + q * 4) = o;     // STG.128 coalesced
                    *(float4*)(sb + n * NH + q * 4) = sp;
                }
            }
            PAIR_BAR(w);
        }
        {   // final tile
            const int dt = NT2 - 1;
            const int s  = w * (QLEN / NH) + (dt >> 2);
            const int h0 = (dt & 3) * HT2;
            const float* src = buf[w][dt & 1];
            float* ob = outp + (((long long)b * NS + s) * NN + g * NPB) * NH + h0;
            float* sb = ob + TOTE;
            #pragma unroll
            for (int it = 0; it < 8; ++it) {
                int idx = lane + it * 32;
                int n = idx >> 3, q = idx & 7;
                float4 v = *(const float4*)(src + n * RS2 + q * 4);
                float th = thr_s[n];
                bool p0 = v.x > th, p1 = v.y > th, p2 = v.z > th, p3 = v.w > th;
                float4 o, sp;
                o.x = p0 ? v.x : 0.0f;  sp.x = p0 ? 1.0f : 0.0f;
                o.y = p1 ? v.y : 0.0f;  sp.y = p1 ? 1.0f : 0.0f;
                o.z = p2 ? v.z : 0.0f;  sp.z = p2 ? 1.0f : 0.0f;
                o.w = p3 ? v.w : 0.0f;  sp.w = p3 ? 1.0f : 0.0f;
                *(float4*)(ob + n * NH + q * 4) = o;
                *(float4*)(sb + n * NH + q * 4) = sp;
            }
        }
    }

    __syncthreads();   // all tiles drained; same-block global writes visible

    // ================= fix-up: warp 0, one lane per neuron =================
    if (wid == 0) {
        const float th = thr_s[lane];
        const int   n  = g * NPB + lane;
        float S = qexit[0][lane];                 // quarter 0 exact
        for (int qq = 1; qq < NQ; ++qq) {
            const int t0 = qq * QLEN;
            bool merged = false;
            for (int i = 0; i < QLEN; ++i) {
                const int t = t0 + i;
                float x = __ldg(xb + t);          // broadcast across lanes
                STEPX(S, x, th);
                bool sp = S > th;
                long long a = (((long long)b * NS + (t >> 7)) * NN + n) * NH + (t & 127);
                float spec = spkp[a];
                if (sp && spec != 0.0f) {         // joint spike -> bitwise merge
                    outp[a] = S;                  // patch value; spike already 1
                    merged = true;
                    break;
                }
                outp[a] = sp ? S : 0.0f;
                spkp[a] = sp ? 1.0f : 0.0f;
            }
            S = merged ? qexit[qq][lane] : S;     // true exit of quarter qq
        }
    }
}

extern "C" void kernel_launch(void* const* d_in, const int* in_sizes, int n_in,
                              void* d_out, int out_size)
{
    const float* inputs   = (const float*)d_in[0];  // [B,S,H]
    const float* threshes = (const float*)d_in[1];  // [N]
    const float* acc0     = (const float*)d_in[2];  // [B,N]
    float* out = (float*)d_out;                     // outs then spikes (f32)

    lif_kernel<<<NB * 2, 256>>>(inputs, threshes, acc0, out);
}

// round 8
// speedup vs baseline: 3.1532x; 2.0117x over previous
#include <cuda_runtime.h>

// Two-phase exact LIF, 2-way time split with renewal speculation.
//
// Exact step on pre-reset S:  f = set.le(S,th); S = fma(S,f,x)   (proven R4+).
// Phase 1 (spec kernel): R4's proven pipeline, 64 blocks = 2 halves x 16b x 2g.
//   Half 0 entry = acc0 (exact); half 1 entry = th+1 (assumed spike => S0=x0).
//   Stores half-0 exit states to __device__ scratch.
// Phase 2 (fix kernel): 1024 lanes, one per chain. Replays BOTH chains in
//   registers over half 1 (true S from stored exit; spec P from th+1, bitwise
//   identical to phase 1), patching out/spike with WRITE-ONLY stores until the
//   first joint spike (renewal merge: states equal from the next step). No
//   data-dependent global loads anywhere; x prefetched 8-ahead.

#define NB 16
#define NS 256
#define NH 128
#define NN 64
#define NPB 32
#define HT 128
#define HALF 16384                 // steps per half
#define SHALF 128                  // s-rows per half
#define RS 132
#define TT (NS * NH)
#define TOTE ((long long)NB * NS * NN * NH)

__device__ float g_exit[NB * 2 * NPB];   // half-0 exit per chain

#define STEPX(S, XV, TH) do {                                               \
    float f_;                                                               \
    asm("set.le.f32.f32 %0, %1, %2;" : "=f"(f_) : "f"(S), "f"(TH));         \
    asm("fma.rn.f32 %0, %1, %2, %3;" : "=f"(S) : "f"(S), "f"(f_), "f"(XV)); \
} while (0)

// ---------------- phase 1: R4 pipeline per half ----------------

__device__ __forceinline__ void drain_tile(
    int b, int g, int s, const float* __restrict__ src,
    const float* __restrict__ thr_s, float* __restrict__ outbuf, int wl)
{
    float* ob = outbuf + (((long long)b * NS + s) * NN + g * NPB) * NH;
    float* sb = ob + TOTE;
    #pragma unroll
    for (int it = 0; it < 16; ++it) {
        int idx = wl + it * 64;
        int n = idx >> 5, q = idx & 31;
        float4 v = *(const float4*)(src + n * RS + q * 4);   // LDS.128
        float th = thr_s[n];
        bool p0 = v.x > th, p1 = v.y > th, p2 = v.z > th, p3 = v.w > th;
        float4 o, sp;
        o.x = p0 ? v.x : 0.0f;  sp.x = p0 ? 1.0f : 0.0f;
        o.y = p1 ? v.y : 0.0f;  sp.y = p1 ? 1.0f : 0.0f;
        o.z = p2 ? v.z : 0.0f;  sp.z = p2 ? 1.0f : 0.0f;
        o.w = p3 ? v.w : 0.0f;  sp.w = p3 ? 1.0f : 0.0f;
        *(float4*)(ob + n * NH + q * 4) = o;                 // STG.128
        *(float4*)(sb + n * NH + q * 4) = sp;
    }
}

__global__ __launch_bounds__(96, 1)
void lif_spec_kernel(const float* __restrict__ inputs,
                     const float* __restrict__ threshes,
                     const float* __restrict__ acc0,
                     float* __restrict__ outbuf)
{
    __shared__ float buf[2][NPB * RS];
    __shared__ float xs[2][HT];
    __shared__ float thr_s[NPB];

    const int c    = blockIdx.x & 1;        // time half
    const int g    = (blockIdx.x >> 1) & 1; // neuron group
    const int b    = blockIdx.x >> 2;       // batch
    const int tid  = threadIdx.x;
    const int wid  = tid >> 5;
    const int lane = tid & 31;
    const int s0   = c * SHALF;
    const float* xb = inputs + (long long)b * TT + (long long)c * HALF;

    if (tid < NPB) thr_s[tid] = threshes[g * NPB + tid];
    if (wid == 1)
        *(float4*)(&xs[0][lane * 4]) = *(const float4*)(xb + lane * 4);
    __syncthreads();

    if (wid == 0) {
        const float th = thr_s[lane];
        float S = (c == 0) ? acc0[b * NN + g * NPB + lane] : (th + 1.0f);
        for (int tt = 0; tt < SHALF; ++tt) {
            const float* __restrict__ xr  = xs[tt & 1];
            float* __restrict__       row = &buf[tt & 1][lane * RS];
            #pragma unroll
            for (int j = 0; j < HT; j += 8) {
                float4 xa = *(const float4*)(xr + j);
                float4 xc = *(const float4*)(xr + j + 4);
                float4 a, e;
                STEPX(S, xa.x, th); a.x = S;
                STEPX(S, xa.y, th); a.y = S;
                STEPX(S, xa.z, th); a.z = S;
                STEPX(S, xa.w, th); a.w = S;
                STEPX(S, xc.x, th); e.x = S;
                STEPX(S, xc.y, th); e.y = S;
                STEPX(S, xc.z, th); e.z = S;
                STEPX(S, xc.w, th); e.w = S;
                *(float4*)(row + j)     = a;
                *(float4*)(row + j + 4) = e;
            }
            __syncthreads();
        }
        if (c == 0) g_exit[(b * 2 + g) * NPB + lane] = S;   // true entry of half 1
    } else {
        const int wl = tid - 32;
        for (int tt = 0; tt < SHALF; ++tt) {
            if (tt + 1 < SHALF && wl < 32)
                *(float4*)(&xs[(tt + 1) & 1][wl * 4]) =
                    *(const float4*)(xb + (tt + 1) * HT + wl * 4);
            if (tt > 0)
                drain_tile(b, g, s0 + tt - 1, buf[(tt - 1) & 1], thr_s, outbuf, wl);
            __syncthreads();
        }
        drain_tile(b, g, s0 + SHALF - 1, buf[(SHALF - 1) & 1], thr_s, outbuf, wl);
    }
}

// ---------------- phase 2: register-only dual-chain fix-up ----------------

__global__ __launch_bounds__(128, 1)
void lif_fix_kernel(const float* __restrict__ inputs,
                    const float* __restrict__ threshes,
                    float* __restrict__ outbuf)
{
    const int w    = blockIdx.x * 4 + (threadIdx.x >> 5);   // 0..31
    const int lane = threadIdx.x & 31;
    const int b    = w >> 1;
    const int g    = w & 1;
    const int n    = g * NPB + lane;
    const float th = threshes[n];
    const float* xq = inputs + (long long)b * TT + HALF;    // half-1 x stream
    float* outp = outbuf;
    float* spkp = outbuf + TOTE;

    float S = g_exit[(b * 2 + g) * NPB + lane];   // true entry of half 1
    float P = th + 1.0f;                          // spec replay, bitwise as phase 1
    const long long A0 = (long long)b * NS * NN * NH + (long long)n * NH;

    bool done = false;
    for (int i0 = 0; i0 < HALF; i0 += 8) {
        float xv[8];                               // independent prefetch, MLP=8
        #pragma unroll
        for (int k = 0; k < 8; ++k) xv[k] = __ldg(xq + i0 + k);
        #pragma unroll
        for (int k = 0; k < 8; ++k) {
            STEPX(S, xv[k], th);                   // true chain
            STEPX(P, xv[k], th);                   // spec replay (independent)
            if (!done) {
                const int t = HALF + i0 + k;
                const long long a = A0 + (long long)(t >> 7) * (NN * NH) + (t & 127);
                bool sp = S > th;
                outp[a] = sp ? S : 0.0f;           // write-only patch
                spkp[a] = sp ? 1.0f : 0.0f;
                if (sp && (P > th)) done = true;   // joint spike: merged after t
            }
        }
        if (__ballot_sync(0xFFFFFFFFu, !done) == 0u) break;
    }
}

extern "C" void kernel_launch(void* const* d_in, const int* in_sizes, int n_in,
                              void* d_out, int out_size)
{
    const float* inputs   = (const float*)d_in[0];  // [B,S,H]
    const float* threshes = (const float*)d_in[1];  // [N]
    const float* acc0     = (const float*)d_in[2];  // [B,N]
    float* out = (float*)d_out;                     // outs then spikes (f32)

    lif_spec_kernel<<<NB * 2 * 2, 96>>>(inputs, threshes, acc0, out);
    lif_fix_kernel<<<8, 128>>>(inputs, threshes, out);
}

// round 9
// speedup vs baseline: 3.6290x; 1.1509x over previous
#include <cuda_runtime.h>

// LIF: R4 skeleton + in-warp 2-way time split via renewal speculation.
//
// Exact step on pre-reset S:  f = set.le(S,th); S = fma(S,f,x)   (proven).
// Lane n runs TWO interleaved chains: half-0 exact from acc0, half-1 spec
// from th+1 (=> S0 = x0 exactly, "assumed spike"). Independent chains fill
// each other's latency: ~13.5 cyc per dual-step, serial span halved.
// Epilogue (same warp): replay half-1 from the true boundary state vs the
// bitwise-identical spec chain (registers only), patching out/spike until
// the first joint spike (then states merge bitwise; stored data is exact).
//
// 32 blocks = 16 batches x 2 neuron-halves. 128 threads:
//   warp 0   : dual chains (one neuron per lane)
//   warp 1   : stages x tiles for both halves
//   warps 2,3: drain both halves' S tiles (coalesced STG.128)
// Tile = 64 steps; 256 periods; 1 __syncthreads per period.

#define NB 16
#define NS 256
#define NH 128
#define NN 64
#define NPB 32
#define HT 64                      // steps per tile
#define NT 256                     // periods (HALF / HT)
#define HALF 16384                 // steps per half
#define RS 68                      // row stride: chunk 17n+q -> conflict-free
#define TT (NS * NH)
#define TOTE ((long long)NB * NS * NN * NH)

#define STEPX(S, XV, TH) do {                                               \
    float f_;                                                               \
    asm("set.le.f32.f32 %0, %1, %2;" : "=f"(f_) : "f"(S), "f"(TH));         \
    asm("fma.rn.f32 %0, %1, %2, %3;" : "=f"(S) : "f"(S), "f"(f_), "f"(XV)); \
} while (0)

// drain one 64-step tile of one half to global (64 writer lanes)
__device__ __forceinline__ void drain_tile(
    int b, int g, int h, int dt, const float* __restrict__ src,
    const float* __restrict__ thr_s, float* __restrict__ outbuf, int wl)
{
    const int s  = h * (HALF / NH) + (dt >> 1);
    const int h0 = (dt & 1) * HT;
    float* ob = outbuf + (((long long)b * NS + s) * NN + g * NPB) * NH + h0;
    float* sb = ob + TOTE;
    #pragma unroll
    for (int it = 0; it < 8; ++it) {
        int idx = wl + it * 64;          // 512 quads: n = idx>>4, q = idx&15
        int n = idx >> 4, q = idx & 15;
        float4 v = *(const float4*)(src + n * RS + q * 4);   // LDS.128
        float th = thr_s[n];
        bool p0 = v.x > th, p1 = v.y > th, p2 = v.z > th, p3 = v.w > th;
        float4 o, sp;
        o.x = p0 ? v.x : 0.0f;  sp.x = p0 ? 1.0f : 0.0f;
        o.y = p1 ? v.y : 0.0f;  sp.y = p1 ? 1.0f : 0.0f;
        o.z = p2 ? v.z : 0.0f;  sp.z = p2 ? 1.0f : 0.0f;
        o.w = p3 ? v.w : 0.0f;  sp.w = p3 ? 1.0f : 0.0f;
        *(float4*)(ob + n * NH + q * 4) = o;                 // STG.128
        *(float4*)(sb + n * NH + q * 4) = sp;
    }
}

__global__ __launch_bounds__(128, 1)
void lif_kernel(const float* __restrict__ inputs,
                const float* __restrict__ threshes,
                const float* __restrict__ acc0,
                float* __restrict__ outbuf)
{
    __shared__ float buf[2][2][NPB * RS];   // [half][dblbuf] 34.8 KB
    __shared__ float xs[2][2][HT];          // [half][dblbuf]  1 KB
    __shared__ float thr_s[NPB];

    const int b    = blockIdx.x >> 1;
    const int g    = blockIdx.x & 1;
    const int tid  = threadIdx.x;
    const int wid  = tid >> 5;
    const int lane = tid & 31;
    const float* xb = inputs + (long long)b * TT;
    float* outp = outbuf;
    float* spkp = outbuf + TOTE;

    if (tid < NPB) thr_s[tid] = threshes[g * NPB + tid];
    if (wid == 1) {                         // stage x tile 0 of both halves
        const int h = lane >> 4, l = lane & 15;
        *(float4*)&xs[h][0][l * 4] = *(const float4*)(xb + h * HALF + l * 4);
    }
    __syncthreads();

    float th = 0.0f, S0 = 0.0f;
    if (wid == 0) { th = thr_s[lane]; S0 = acc0[b * NN + g * NPB + lane]; }
    float S1 = th + 1.0f;                   // spec entry: first step -> x0 exactly

    for (int tt = 0; tt < NT; ++tt) {
        if (wid == 0) {
            // ---------- dual chains: tile tt of half0 and half1 ----------
            const float* __restrict__ x0 = xs[0][tt & 1];
            const float* __restrict__ x1 = xs[1][tt & 1];
            float* __restrict__ r0 = &buf[0][tt & 1][lane * RS];
            float* __restrict__ r1 = &buf[1][tt & 1][lane * RS];
            #pragma unroll
            for (int j = 0; j < HT; j += 8) {
                float4 a0 = *(const float4*)(x0 + j);
                float4 c0 = *(const float4*)(x0 + j + 4);
                float4 a1 = *(const float4*)(x1 + j);
                float4 c1 = *(const float4*)(x1 + j + 4);
                float4 o0a, o0c, o1a, o1c;
                STEPX(S0, a0.x, th); o0a.x = S0;  STEPX(S1, a1.x, th); o1a.x = S1;
                STEPX(S0, a0.y, th); o0a.y = S0;  STEPX(S1, a1.y, th); o1a.y = S1;
                STEPX(S0, a0.z, th); o0a.z = S0;  STEPX(S1, a1.z, th); o1a.z = S1;
                STEPX(S0, a0.w, th); o0a.w = S0;  STEPX(S1, a1.w, th); o1a.w = S1;
                STEPX(S0, c0.x, th); o0c.x = S0;  STEPX(S1, c1.x, th); o1c.x = S1;
                STEPX(S0, c0.y, th); o0c.y = S0;  STEPX(S1, c1.y, th); o1c.y = S1;
                STEPX(S0, c0.z, th); o0c.z = S0;  STEPX(S1, c1.z, th); o1c.z = S1;
                STEPX(S0, c0.w, th); o0c.w = S0;  STEPX(S1, c1.w, th); o1c.w = S1;
                *(float4*)(r0 + j)     = o0a;     *(float4*)(r0 + j + 4) = o0c;
                *(float4*)(r1 + j)     = o1a;     *(float4*)(r1 + j + 4) = o1c;
            }
        } else if (wid == 1) {
            // ---------- stager: next x tiles for both halves ----------
            if (tt + 1 < NT) {
                const int h = lane >> 4, l = lane & 15;
                *(float4*)&xs[h][(tt + 1) & 1][l * 4] =
                    *(const float4*)(xb + h * HALF + (tt + 1) * HT + l * 4);
            }
        } else {
            // ---------- writers: drain previous period, both halves ----------
            const int wl = tid - 64;       // 0..63
            if (tt > 0) {
                drain_tile(b, g, 0, tt - 1, buf[0][(tt - 1) & 1], thr_s, outp, wl);
                drain_tile(b, g, 1, tt - 1, buf[1][(tt - 1) & 1], thr_s, outp, wl);
            }
        }
        __syncthreads();
    }
    if (wid >= 2) {                         // final period drains
        const int wl = tid - 64;
        drain_tile(b, g, 0, NT - 1, buf[0][(NT - 1) & 1], thr_s, outp, wl);
        drain_tile(b, g, 1, NT - 1, buf[1][(NT - 1) & 1], thr_s, outp, wl);
    }
    __syncthreads();                        // all drains visible before patching

    // ---------- epilogue fix-up: warp 0, register-only dual replay ----------
    if (wid == 0) {
        const int n = g * NPB + lane;
        float S = S0;                       // true entry of half 1
        float P = th + 1.0f;                // spec replay, bitwise as main loop
        const float* xq = xb + HALF;
        bool done = false;
        for (int i0 = 0; i0 < HALF; i0 += 8) {
            float xv[8];
            #pragma unroll
            for (int k = 0; k < 8; ++k) xv[k] = __ldg(xq + i0 + k);   // broadcast
            #pragma unroll
            for (int k = 0; k < 8; ++k) {
                STEPX(S, xv[k], th);
                STEPX(P, xv[k], th);
                if (!done) {
                    const int t = HALF + i0 + k;
                    const long long a =
                        (((long long)b * NS + (t >> 7)) * NN + n) * NH + (t & 127);
                    bool sp = S > th;
                    outp[a] = sp ? S : 0.0f;
                    spkp[a] = sp ? 1.0f : 0.0f;
                    if (sp && (P > th)) done = true;   // joint spike: merged
                }
            }
            if (__ballot_sync(0xFFFFFFFFu, !done) == 0u) break;
        }
    }
}

extern "C" void kernel_launch(void* const* d_in, const int* in_sizes, int n_in,
                              void* d_out, int out_size)
{
    const float* inputs   = (const float*)d_in[0];  // [B,S,H]
    const float* threshes = (const float*)d_in[1];  // [N]
    const float* acc0     = (const float*)d_in[2];  // [B,N]
    float* out = (float*)d_out;                     // outs then spikes (f32)

    lif_kernel<<<NB * 2, 128>>>(inputs, threshes, acc0, out);
}

// round 10
// speedup vs baseline: 25.5209x; 7.0324x over previous
#include <cuda_runtime.h>

// LIF, exact k=4 renewal-group folding inside the R4 pipelined skeleton.
//
// Exact step on pre-reset S: f = set.le(S,th); S = fma(S,f,x).
// Group of 4 steps from entry S with inputs x1..x4:
//   u1=S+x1; u2=u1+x2; u3=u2+x3            (speculative no-spike FADD chain)
//   a  = fma(u3, [u3<=th], x4)             (exact step-4 fold)
//   a2 = (u2>th) ? T2 : a                  (T2 = tail of restart at x3: 1 STEPX)
//   a1 = (u1>th) ? T1 : a2                 (T1 = tail of restart at x2: 2 STEPX)
//   S' = (S >th) ? T0 : a1                 (T0 = tail of restart at x1: 3 STEPX)
// First-crossing-from-left semantics; every branch value is the exact
// sequential-fadd result (T tables computed with the exact STEPX recurrence).
// Critical path ~9 cyc/step vs 13.9 for the 1-step chain.
//
// 32 blocks = 16 batches x 2 neuron-halves (32 chains/block). 256 threads:
//   wid4: chain warp (one chain per lane), group folding, stores group entries
//   wid5/6: T-table helpers (even/odd groups) for tile t+1
//   wid1/2: rerun warps (even/odd groups): exact per-step S of tile t-1
//   wid3/7: drain warps: out = v*set.gt(v,th), spike = set.gt(v,th), STG.128
//   wid0: x stager (tile t+2)
// One __syncthreads per 64-step tile.

#define NB 16
#define NS 256
#define NH 128
#define NN 64
#define NPB 32
#define HT 64
#define NTILES 512
#define GPT 16                      // k=4 groups per tile
#define RS 68                       // sbuf row stride: 16B chunk 17n+q, conflict-free
#define TT (NS * NH)
#define TOTE ((long long)NB * NS * NN * NH)

#define STEPX(S, XV, TH) do {                                               \
    float f_;                                                               \
    asm("set.le.f32.f32 %0, %1, %2;" : "=f"(f_) : "f"(S), "f"(TH));         \
    asm("fma.rn.f32 %0, %1, %2, %3;" : "=f"(S) : "f"(S), "f"(f_), "f"(XV)); \
} while (0)

#define SELGT(R, V, TH, TRU, FAL)                                           \
    asm("{ .reg .pred p_; setp.gt.f32 p_, %1, %2; selp.f32 %0, %3, %4, p_; }" \
        : "=f"(R) : "f"(V), "f"(TH), "f"(TRU), "f"(FAL))

__global__ __launch_bounds__(256, 1)
void lif_kernel(const float* __restrict__ inputs,
                const float* __restrict__ threshes,
                const float* __restrict__ acc0,
                float* __restrict__ outbuf)
{
    __shared__ float  xs[4][HT];             // x ring (t-1, t, t+1, t+2)
    __shared__ float4 Tq[2][GPT][NPB];       // T-quads {T0,T1,T2,-}
    __shared__ float  entries[2][GPT][NPB];  // group-entry S
    __shared__ float  sbuf[2][NPB * RS];     // rerun per-step S tiles
    __shared__ float  thr[NPB];

    const int b    = blockIdx.x >> 1;
    const int g    = blockIdx.x & 1;
    const int tid  = threadIdx.x;
    const int wid  = tid >> 5;
    const int lane = tid & 31;
    const float* xb = inputs + (long long)b * TT;
    float* outp = outbuf;
    float* spkp = outbuf + TOTE;

    // ---- prologue 1: stage x(0), x(1); load thresholds ----
    if (wid == 0) {
        if (lane < 16)
            *(float4*)&xs[0][lane * 4] = *(const float4*)(xb + lane * 4);
        else {
            int l = lane - 16;
            *(float4*)&xs[1][l * 4] = *(const float4*)(xb + HT + l * 4);
        }
    }
    if (wid == 1) thr[lane] = threshes[g * NPB + lane];
    __syncthreads();

    const float th = thr[lane];              // lane == chain index everywhere

    // ---- prologue 2: T(0); chain loads acc0 ----
    float S = 0.0f;
    if (wid == 5 || wid == 6) {
        const int par = wid - 5;
        #pragma unroll
        for (int gg = 0; gg < 8; ++gg) {
            const int grp = gg * 2 + par;
            float4 xq = *(const float4*)&xs[0][grp * 4];
            float T2 = xq.z;  STEPX(T2, xq.w, th);
            float T1 = xq.y;  STEPX(T1, xq.z, th);  STEPX(T1, xq.w, th);
            float T0 = xq.x;  STEPX(T0, xq.y, th);  STEPX(T0, xq.z, th);
            STEPX(T0, xq.w, th);
            Tq[0][grp][lane] = make_float4(T0, T1, T2, 0.0f);
        }
    }
    if (wid == 4) S = acc0[b * NN + g * NPB + lane];
    __syncthreads();

    for (int t = 0; t <= NTILES + 1; ++t) {
        if (wid == 4) {
            // ================= chain warp: tile t =================
            if (t < NTILES) {
                const float*  __restrict__ xr = xs[t & 3];
                const float4* __restrict__ Tt = &Tq[t & 1][0][0];
                float* __restrict__ ent = &entries[t & 1][0][0];
                #pragma unroll
                for (int grp = 0; grp < GPT; ++grp) {
                    float4 xq = *(const float4*)&xr[grp * 4];     // broadcast
                    float4 Tv = Tt[grp * NPB + lane];             // LDS.128
                    ent[grp * NPB + lane] = S;                    // group entry
                    float u1 = S + xq.x;
                    float u2 = u1 + xq.y;
                    float u3 = u2 + xq.z;
                    float f3, a, a2, a1, Sn;
                    asm("set.le.f32.f32 %0, %1, %2;" : "=f"(f3) : "f"(u3), "f"(th));
                    asm("fma.rn.f32 %0, %1, %2, %3;" : "=f"(a)
                        : "f"(u3), "f"(f3), "f"(xq.w));
                    SELGT(a2, u2, th, Tv.z, a);
                    SELGT(a1, u1, th, Tv.y, a2);
                    SELGT(Sn, S,  th, Tv.x, a1);
                    S = Sn;
                }
            }
        } else if (wid == 0) {
            // ================= x stager: tile t+2 =================
            if (t + 2 < NTILES && lane < 16)
                *(float4*)&xs[(t + 2) & 3][lane * 4] =
                    *(const float4*)(xb + (t + 2) * HT + lane * 4);
        } else if (wid == 5 || wid == 6) {
            // ================= T helpers: tile t+1 =================
            if (t + 1 < NTILES) {
                const int par = wid - 5;
                const float* __restrict__ xr = xs[(t + 1) & 3];
                #pragma unroll
                for (int gg = 0; gg < 8; ++gg) {
                    const int grp = gg * 2 + par;
                    float4 xq = *(const float4*)&xr[grp * 4];
                    float T2 = xq.z;  STEPX(T2, xq.w, th);
                    float T1 = xq.y;  STEPX(T1, xq.z, th);  STEPX(T1, xq.w, th);
                    float T0 = xq.x;  STEPX(T0, xq.y, th);  STEPX(T0, xq.z, th);
                    STEPX(T0, xq.w, th);
                    Tq[(t + 1) & 1][grp][lane] = make_float4(T0, T1, T2, 0.0f);
                }
            }
        } else if (wid == 1 || wid == 2) {
            // ================= rerun warps: tile t-1 =================
            if (t >= 1 && t <= NTILES) {
                const int par = wid - 1;
                const int pt  = (t - 1) & 1;
                const float* __restrict__ xr  = xs[(t - 1) & 3];
                const float* __restrict__ ent = &entries[pt][0][0];
                float* __restrict__ sb = sbuf[pt];
                #pragma unroll
                for (int gg = 0; gg < 8; ++gg) {
                    const int grp = gg * 2 + par;
                    float  E  = ent[grp * NPB + lane];
                    float4 xq = *(const float4*)&xr[grp * 4];
                    float4 o;
                    float  P = E;
                    STEPX(P, xq.x, th); o.x = P;
                    STEPX(P, xq.y, th); o.y = P;
                    STEPX(P, xq.z, th); o.z = P;
                    STEPX(P, xq.w, th); o.w = P;
                    *(float4*)&sb[lane * RS + grp * 4] = o;       // STS.128
                }
            }
        } else {
            // ================= drain warps (wid 3,7): tile t-2 =================
            if (t >= 2) {
                const int dt = t - 2;
                const int pt = dt & 1;
                const int s  = dt >> 1;
                const int h0 = (dt & 1) * HT;
                const int idx0 = (wid == 7) ? 256 : 0;
                const float* __restrict__ sb = sbuf[pt];
                float* ob = outp + (((long long)b * NS + s) * NN + g * NPB) * NH + h0;
                float* sp = ob + TOTE;
                #pragma unroll
                for (int i = 0; i < 8; ++i) {
                    int idx = idx0 + i * 32 + lane;   // n = idx>>4, q = idx&15
                    int n = idx >> 4, q = idx & 15;
                    float4 v = *(const float4*)&sb[n * RS + q * 4];
                    float tn = thr[n];
                    float f0, f1, f2, f3;
                    asm("set.gt.f32.f32 %0, %1, %2;" : "=f"(f0) : "f"(v.x), "f"(tn));
                    asm("set.gt.f32.f32 %0, %1, %2;" : "=f"(f1) : "f"(v.y), "f"(tn));
                    asm("set.gt.f32.f32 %0, %1, %2;" : "=f"(f2) : "f"(v.z), "f"(tn));
                    asm("set.gt.f32.f32 %0, %1, %2;" : "=f"(f3) : "f"(v.w), "f"(tn));
                    float4 o = make_float4(v.x * f0, v.y * f1, v.z * f2, v.w * f3);
                    float4 k = make_float4(f0, f1, f2, f3);
                    *(float4*)(ob + n * NH + q * 4) = o;          // STG.128
                    *(float4*)(sp + n * NH + q * 4) = k;
                }
            }
        }
        __syncthreads();
    }
}

extern "C" void kernel_launch(void* const* d_in, const int* in_sizes, int n_in,
                              void* d_out, int out_size)
{
    const float* inputs   = (const float*)d_in[0];  // [B,S,H]
    const float* threshes = (const float*)d_in[1];  // [N]
    const float* acc0     = (const float*)d_in[2];  // [B,N]
    float* out = (float*)d_out;                     // outs then spikes (f32)

    lif_kernel<<<NB * 2, 256>>>(inputs, threshes, acc0, out);
}